// round 16
// baseline (speedup 1.0000x reference)
#include <cuda_runtime.h>
#include <cstdint>

#define MARGIN 0.1f
#define TPB 64           // 2 warps, ONE row per CTA: perfect slot backfill
#define P1U 2            // pass-1: int4 loads per thread between votes (512 elems/chunk)
#define P2U 4            // pass-2 unroll
#define NSLOT 32

// Scattered accumulator slots (128B apart -> distinct L2 slices, no atomic
// serialization at one address). Zero at module load; the LAST CTA resets
// them after producing the output, so every invocation (correctness call,
// capture call, each graph replay) observes identical initial state.
struct Slot { float total; float count; float pad[30]; };   // 128 bytes
__device__ Slot g_slots[NSLOT];
__device__ unsigned int g_done;

__global__ void __launch_bounds__(TPB) hinge_row_kernel(
    const float* __restrict__ scores,
    const int* __restrict__ lens,
    const int* __restrict__ labels,
    int L, int B,
    float* __restrict__ out)
{
    const int t = threadIdx.x;
    const int lane = t & 31;
    const int wid = t >> 5;
    const int row = blockIdx.x;

    const int len = lens[row];          // CTA-uniform
    // NOTE: no early return — every CTA must reach the done-counter below.

    if (len > 0) {
        const size_t base = (size_t)row * (size_t)L;
        const float*  __restrict__ srow  = scores + base;
        const float4* __restrict__ srow4 = (const float4*)srow;
        const int4*   __restrict__ lrow4 = (const int4*)(labels + base);
        const int nv = (len + 3) >> 2;  // live float4/int4 prefix

        __shared__ float sh_ps[2];
        __shared__ int   sh_pc[2];
        __shared__ float sh_hs[2];

        // ---- pass 1: both warps scan labels for the (at most one) positive;
        //      block-wide vote to early-exit. ----
        float pos_sum = 0.0f;
        int   pos_cnt = 0;
        int   found = 0;
        for (int v0 = 0; v0 < nv; v0 += TPB * P1U) {
            int4 lv[P1U];
#pragma unroll
            for (int u = 0; u < P1U; u++) {
                const int v = v0 + u * TPB + t;
                lv[u] = (v < nv) ? lrow4[v] : make_int4(0, 0, 0, 0);
            }
#pragma unroll
            for (int u = 0; u < P1U; u++) {
                const int v = v0 + u * TPB + t;
                const int j0 = v << 2;
                const int le[4] = { lv[u].x, lv[u].y, lv[u].z, lv[u].w };
#pragma unroll
                for (int e = 0; e < 4; e++) {
                    const int j = j0 + e;
                    if (j < len && le[e] == 1) {
                        pos_sum += srow[j];     // rare predicated gather
                        pos_cnt++;
                        found = 1;
                    }
                }
            }
            if (__syncthreads_or(found)) break;  // ≤1 positive per row
        }
        // block reduce pos_sum / pos_cnt (2 warps)
#pragma unroll
        for (int o = 16; o > 0; o >>= 1) {
            pos_sum += __shfl_xor_sync(0xFFFFFFFFu, pos_sum, o);
            pos_cnt += __shfl_xor_sync(0xFFFFFFFFu, pos_cnt, o);
        }
        if (lane == 0) { sh_ps[wid] = pos_sum; sh_pc[wid] = pos_cnt; }
        __syncthreads();
        const float ps = sh_ps[0] + sh_ps[1];
        const int   pc = sh_pc[0] + sh_pc[1];
        const float chosen = (pc > 0) ? ps : -MARGIN;

        // ---- pass 2: hinge over ALL valid elements, unrolled for MLP.
        //      (Labels not needed: the positive's hinge is exactly MARGIN,
        //      subtracted at the end.) ----
        float hs = 0.0f;
        for (int v0 = 0; v0 < nv; v0 += TPB * P2U) {
            float4 a[P2U];
#pragma unroll
            for (int u = 0; u < P2U; u++) {
                const int v = v0 + u * TPB + t;
                a[u] = (v < nv) ? srow4[v] : make_float4(0.f, 0.f, 0.f, 0.f);
            }
#pragma unroll
            for (int u = 0; u < P2U; u++) {
                const int j0 = (v0 + u * TPB + t) << 2;
                const float se[4] = { a[u].x, a[u].y, a[u].z, a[u].w };
#pragma unroll
                for (int e = 0; e < 4; e++)
                    if (j0 + e < len)
                        hs += fmaxf(MARGIN + se[e] - chosen, 0.0f);
            }
        }
#pragma unroll
        for (int o = 16; o > 0; o >>= 1)
            hs += __shfl_down_sync(0xFFFFFFFFu, hs, o);
        if (lane == 0) sh_hs[wid] = hs;
        __syncthreads();

        if (t == 0) {
            const float h = sh_hs[0] + sh_hs[1];
            const int neg_cnt = len - pc;        // valid elems minus positives
            if (neg_cnt > 0) {                   // valid_obs = (len>0) & has_neg
                const float hs_neg = h - MARGIN * (float)pc;
                Slot* sl = &g_slots[row & (NSLOT - 1)];
                atomicAdd(&sl->total, hs_neg / (float)neg_cnt);
                atomicAdd(&sl->count, 1.0f);
            }
        }
    }

    // ---- fused finalize: one acq_rel L2 atomic per CTA (t==0 only).
    //      Release orders this CTA's slot atomics before the increment;
    //      acquire on the last increment makes all slot writes visible. ----
    if (t == 0) {
        unsigned int d;
        asm volatile("atom.acq_rel.gpu.add.u32 %0, [%1], 1;"
                     : "=r"(d) : "l"(&g_done) : "memory");
        if (d == (unsigned int)(B - 1)) {
            float T = 0.0f, C = 0.0f;
#pragma unroll
            for (int i = 0; i < NSLOT; i++) {
                volatile Slot* sl = &g_slots[i];
                T += sl->total;
                C += sl->count;
                sl->total = 0.0f;       // reset for next launch / graph replay
                sl->count = 0.0f;
            }
            out[0] = (C > 0.0f) ? (T / fmaxf(C, 1.0f)) : 0.0f;
            __threadfence();            // one CTA only: order resets before
            *((volatile unsigned int*)&g_done) = 0u;   // counter re-arm
        }
    }
}

extern "C" void kernel_launch(void* const* d_in, const int* in_sizes, int n_in,
                              void* d_out, int out_size)
{
    const float* scores = (const float*)d_in[0];
    const int*   lens   = (const int*)d_in[1];
    const int*   labels = (const int*)d_in[2];
    float* out = (float*)d_out;

    const int B = in_sizes[1];            // candidate_lengths element count
    const int L = in_sizes[0] / B;        // 2048

    hinge_row_kernel<<<B, TPB>>>(scores, lens, labels, L, B, out);
}

// round 17
// speedup vs baseline: 1.1901x; 1.1901x over previous
#include <cuda_runtime.h>
#include <cstdint>

#define MARGIN 0.1f
#define TPB 64           // 2 warps, ONE row per CTA: perfect slot backfill
#define P1U 2            // pass-1: int4 loads per thread between votes (512 elems/chunk)
#define P2U 4            // pass-2 unroll
#define NSLOT 32

// Scattered accumulator slots (128B apart -> distinct L2 slices, no atomic
// serialization at one address). Zero at module load; hinge_final_kernel
// resets them after each launch so every invocation sees identical state.
struct Slot { float total; float count; float pad[30]; };   // 128 bytes
__device__ Slot g_slots[NSLOT];

__global__ void __launch_bounds__(TPB) hinge_row_kernel(
    const float* __restrict__ scores,
    const int* __restrict__ lens,
    const int* __restrict__ labels,
    int L, int B)
{
    const int t = threadIdx.x;
    const int lane = t & 31;
    const int wid = t >> 5;
    const int row = blockIdx.x;
    if (row >= B) return;

    const int len = lens[row];          // CTA-uniform
    if (len <= 0) return;               // no valid observation, contributes 0

    const size_t base = (size_t)row * (size_t)L;
    const float*  __restrict__ srow  = scores + base;
    const float4* __restrict__ srow4 = (const float4*)srow;
    const int4*   __restrict__ lrow4 = (const int4*)(labels + base);
    const int nv  = (len + 3) >> 2;     // live prefix incl. partial vector
    const int nvf = len >> 2;           // fully-valid vectors (all 4 elems < len)

    __shared__ float sh_ps[2];
    __shared__ int   sh_pc[2];
    __shared__ float sh_hs[2];

    // ---- pass 1: both warps scan labels for the (at most one) positive;
    //      block-wide vote to early-exit. Per-element len check kept: the
    //      positive may sit in the boundary vector but beyond len. ----
    float pos_sum = 0.0f;
    int   pos_cnt = 0;
    int   found = 0;
    for (int v0 = 0; v0 < nv; v0 += TPB * P1U) {
        int4 lv[P1U];
#pragma unroll
        for (int u = 0; u < P1U; u++) {
            const int v = v0 + u * TPB + t;
            lv[u] = (v < nv) ? lrow4[v] : make_int4(0, 0, 0, 0);
        }
#pragma unroll
        for (int u = 0; u < P1U; u++) {
            const int v = v0 + u * TPB + t;
            const int j0 = v << 2;
            const int le[4] = { lv[u].x, lv[u].y, lv[u].z, lv[u].w };
#pragma unroll
            for (int e = 0; e < 4; e++) {
                const int j = j0 + e;
                if (j < len && le[e] == 1) {
                    pos_sum += srow[j];     // rare predicated gather
                    pos_cnt++;
                    found = 1;
                }
            }
        }
        if (__syncthreads_or(found)) break;  // ≤1 positive per row
    }
    // block reduce pos_sum / pos_cnt (2 warps)
#pragma unroll
    for (int o = 16; o > 0; o >>= 1) {
        pos_sum += __shfl_xor_sync(0xFFFFFFFFu, pos_sum, o);
        pos_cnt += __shfl_xor_sync(0xFFFFFFFFu, pos_cnt, o);
    }
    if (lane == 0) { sh_ps[wid] = pos_sum; sh_pc[wid] = pos_cnt; }
    __syncthreads();
    const float ps = sh_ps[0] + sh_ps[1];
    const int   pc = sh_pc[0] + sh_pc[1];
    const float chosen = (pc > 0) ? ps : -MARGIN;

    // ---- pass 2: hinge over ALL valid elements.
    //      Full vectors need NO per-element predication; out-of-range slots
    //      are filled with -1e30 so fmaxf contributes 0. Tail (<=3 scalar
    //      elements) handled by threads 0-2. (Labels not needed: the
    //      positive's hinge is exactly MARGIN, subtracted at the end.) ----
    float hs = 0.0f;
    const float mc = MARGIN - chosen;
    for (int v0 = 0; v0 < nvf; v0 += TPB * P2U) {
        float4 a[P2U];
#pragma unroll
        for (int u = 0; u < P2U; u++) {
            const int v = v0 + u * TPB + t;
            a[u] = (v < nvf) ? srow4[v]
                             : make_float4(-1e30f, -1e30f, -1e30f, -1e30f);
        }
#pragma unroll
        for (int u = 0; u < P2U; u++) {
            hs += fmaxf(mc + a[u].x, 0.0f);
            hs += fmaxf(mc + a[u].y, 0.0f);
            hs += fmaxf(mc + a[u].z, 0.0f);
            hs += fmaxf(mc + a[u].w, 0.0f);
        }
    }
    {   // tail: elements [nvf*4, len), at most 3
        const int j = (nvf << 2) + t;
        if (j < len)
            hs += fmaxf(mc + srow[j], 0.0f);
    }
#pragma unroll
    for (int o = 16; o > 0; o >>= 1)
        hs += __shfl_down_sync(0xFFFFFFFFu, hs, o);
    if (lane == 0) sh_hs[wid] = hs;
    __syncthreads();

    if (t == 0) {
        const float h = sh_hs[0] + sh_hs[1];
        const int neg_cnt = len - pc;            // valid elems minus positives
        if (neg_cnt > 0) {                       // valid_obs = (len>0) & has_neg
            const float hs_neg = h - MARGIN * (float)pc;
            Slot* sl = &g_slots[row & (NSLOT - 1)];
            atomicAdd(&sl->total, hs_neg / (float)neg_cnt);
            atomicAdd(&sl->count, 1.0f);
        }
    }
}

__global__ void __launch_bounds__(32) hinge_final_kernel(float* __restrict__ out)
{
    const int i = threadIdx.x;                 // 32 threads, one slot each
    float T = g_slots[i].total;
    float C = g_slots[i].count;
    g_slots[i].total = 0.0f;                   // reset for next launch / replay
    g_slots[i].count = 0.0f;
#pragma unroll
    for (int o = 16; o > 0; o >>= 1) {
        T += __shfl_down_sync(0xFFFFFFFFu, T, o);
        C += __shfl_down_sync(0xFFFFFFFFu, C, o);
    }
    if (i == 0)
        out[0] = (C > 0.0f) ? (T / fmaxf(C, 1.0f)) : 0.0f;
}

extern "C" void kernel_launch(void* const* d_in, const int* in_sizes, int n_in,
                              void* d_out, int out_size)
{
    const float* scores = (const float*)d_in[0];
    const int*   lens   = (const int*)d_in[1];
    const int*   labels = (const int*)d_in[2];
    float* out = (float*)d_out;

    const int B = in_sizes[1];            // candidate_lengths element count
    const int L = in_sizes[0] / B;        // 2048

    hinge_row_kernel<<<B, TPB>>>(scores, lens, labels, L, B);
    hinge_final_kernel<<<1, 32>>>(out);
}